// round 1
// baseline (speedup 1.0000x reference)
#include <cuda_runtime.h>
#include <math.h>

#define NN 30000
#define EE 480000
#define EA (EE + NN)
#define C 64

// ---------------- scratch (static device globals; no allocation) ------------
__device__ __align__(16) float g_x0[NN * C];
__device__ __align__(16) float g_x1[NN * C];
__device__ __align__(16) float g_xl[NN * C];
__device__ __align__(16) float g_xr[NN * C];
__device__ float g_xl8[NN];
__device__ float g_xr8[NN];
__device__ int   g_cnt[NN];
__device__ float g_wsum[NN];
__device__ float g_loop[NN];
__device__ int   g_offs[NN + 1];
__device__ int   g_cursor[NN];
__device__ int   g_csrc[EA];
__device__ float g_cattr[EA];

// ---------------- graph preprocessing ---------------------------------------
__global__ void zero_kernel(float* out, int n) {
    int i = blockIdx.x * blockDim.x + threadIdx.x;
    if (i < n) { g_cnt[i] = 0; g_wsum[i] = 0.f; }
    if (i == 0) out[0] = 0.f;
}

__global__ void hist_kernel(const int* __restrict__ dst,
                            const float* __restrict__ w, int e) {
    int i = blockIdx.x * blockDim.x + threadIdx.x;
    if (i >= e) return;
    int d = dst[i];
    atomicAdd(&g_cnt[d], 1);
    atomicAdd(&g_wsum[d], w[i]);
}

__global__ void loop_attr_kernel(int n) {
    int i = blockIdx.x * blockDim.x + threadIdx.x;
    if (i >= n) return;
    g_loop[i] = g_wsum[i] / fmaxf((float)g_cnt[i], 1.0f);
}

// single-block exclusive scan of (cnt[i]+1)  -> g_offs
__global__ void scan_kernel(int n) {
    __shared__ int sw[32];
    __shared__ int scarry;
    int tid = threadIdx.x, lane = tid & 31, wid = tid >> 5;
    if (tid == 0) scarry = 0;
    __syncthreads();
    for (int base = 0; base < n; base += 1024) {
        int i = base + tid;
        int v = (i < n) ? (g_cnt[i] + 1) : 0;
        int xinc = v;
        #pragma unroll
        for (int o = 1; o < 32; o <<= 1) {
            int y = __shfl_up_sync(0xffffffffu, xinc, o);
            if (lane >= o) xinc += y;
        }
        if (lane == 31) sw[wid] = xinc;
        __syncthreads();
        if (wid == 0) {
            int y = sw[lane];
            #pragma unroll
            for (int o = 1; o < 32; o <<= 1) {
                int z = __shfl_up_sync(0xffffffffu, y, o);
                if (lane >= o) y += z;
            }
            sw[lane] = y;
        }
        __syncthreads();
        int warpoff = (wid > 0) ? sw[wid - 1] : 0;
        int excl = xinc - v + warpoff;
        if (i < n) g_offs[i] = scarry + excl;
        int total = sw[31];
        __syncthreads();
        if (tid == 0) scarry += total;
        __syncthreads();
    }
    if (threadIdx.x == 0) g_offs[n] = scarry;
}

__global__ void cursor_kernel(int n) {
    int i = blockIdx.x * blockDim.x + threadIdx.x;
    if (i < n) g_cursor[i] = g_offs[i];
}

__global__ void scatter_edges_kernel(const int* __restrict__ src,
                                     const int* __restrict__ dst,
                                     const float* __restrict__ w, int e) {
    int i = blockIdx.x * blockDim.x + threadIdx.x;
    if (i >= e) return;
    int d = dst[i];
    int p = atomicAdd(&g_cursor[d], 1);
    g_csrc[p] = src[i];
    g_cattr[p] = w[i];
}

__global__ void scatter_loops_kernel(int n) {
    int i = blockIdx.x * blockDim.x + threadIdx.x;
    if (i >= n) return;
    int p = atomicAdd(&g_cursor[i], 1);
    g_csrc[p] = i;
    g_cattr[p] = g_loop[i];
}

// ---------------- GEMM: xl = x@Wl+bl, xr = x@Wr+br (64x64 weights) ----------
// Block: 256 threads, 32 rows x 64 cols per block. Warp w handles cols [8w,8w+8).
__global__ __launch_bounds__(256) void gemm_xlxr_kernel(
    const float* __restrict__ x,
    const float* __restrict__ Wl, const float* __restrict__ bl,
    const float* __restrict__ Wr, const float* __restrict__ br,
    float* __restrict__ xl, float* __restrict__ xr, int n)
{
    __shared__ __align__(16) float sWl[64 * 64];
    __shared__ __align__(16) float sWr[64 * 64];
    __shared__ float sx[32 * 65];
    int tid = threadIdx.x;
    int lane = tid & 31, wid = tid >> 5;
    int rowbase = blockIdx.x * 32;
    for (int i = tid; i < 4096; i += 256) { sWl[i] = Wl[i]; sWr[i] = Wr[i]; }
    for (int i = tid; i < 32 * 64; i += 256) {
        int r = i >> 6, k = i & 63;
        int row = rowbase + r;
        sx[r * 65 + k] = (row < n) ? x[row * 64 + k] : 0.f;
    }
    __syncthreads();
    int c0 = wid * 8;
    float accl[8], accr[8];
    #pragma unroll
    for (int i = 0; i < 8; i++) { accl[i] = __ldg(&bl[c0 + i]); accr[i] = __ldg(&br[c0 + i]); }
    #pragma unroll 16
    for (int k = 0; k < 64; k++) {
        float xv = sx[lane * 65 + k];
        float4 wl0 = *(const float4*)(sWl + k * 64 + c0);
        float4 wl1 = *(const float4*)(sWl + k * 64 + c0 + 4);
        float4 wr0 = *(const float4*)(sWr + k * 64 + c0);
        float4 wr1 = *(const float4*)(sWr + k * 64 + c0 + 4);
        accl[0] = fmaf(xv, wl0.x, accl[0]); accl[1] = fmaf(xv, wl0.y, accl[1]);
        accl[2] = fmaf(xv, wl0.z, accl[2]); accl[3] = fmaf(xv, wl0.w, accl[3]);
        accl[4] = fmaf(xv, wl1.x, accl[4]); accl[5] = fmaf(xv, wl1.y, accl[5]);
        accl[6] = fmaf(xv, wl1.z, accl[6]); accl[7] = fmaf(xv, wl1.w, accl[7]);
        accr[0] = fmaf(xv, wr0.x, accr[0]); accr[1] = fmaf(xv, wr0.y, accr[1]);
        accr[2] = fmaf(xv, wr0.z, accr[2]); accr[3] = fmaf(xv, wr0.w, accr[3]);
        accr[4] = fmaf(xv, wr1.x, accr[4]); accr[5] = fmaf(xv, wr1.y, accr[5]);
        accr[6] = fmaf(xv, wr1.z, accr[6]); accr[7] = fmaf(xv, wr1.w, accr[7]);
    }
    int row = rowbase + lane;
    if (row < n) {
        float4* pl = (float4*)(xl + row * 64 + c0);
        pl[0] = make_float4(accl[0], accl[1], accl[2], accl[3]);
        pl[1] = make_float4(accl[4], accl[5], accl[6], accl[7]);
        float4* pr = (float4*)(xr + row * 64 + c0);
        pr[0] = make_float4(accr[0], accr[1], accr[2], accr[3]);
        pr[1] = make_float4(accr[4], accr[5], accr[6], accr[7]);
    }
}

// -------- fused attention + aggregation: warp per node, online softmax ------
__global__ __launch_bounds__(256) void aggr_kernel(
    const float* __restrict__ xl, const float* __restrict__ xr,
    const float* __restrict__ We, const float* __restrict__ att,
    const float* __restrict__ bo, float* __restrict__ out, int n)
{
    int warp = (blockIdx.x * blockDim.x + threadIdx.x) >> 5;
    int lane = threadIdx.x & 31;
    if (warp >= n) return;
    int node = warp;
    float2 xrv = ((const float2*)(xr + node * 64))[lane];
    float2 Wev = __ldg(((const float2*)We) + lane);
    float2 attv = __ldg(((const float2*)att) + lane);
    int beg = g_offs[node], end = g_offs[node + 1];
    float m = -3.0e38f, s = 0.f, a0 = 0.f, a1 = 0.f;
    for (int j = beg; j < end; ++j) {
        int srcn = g_csrc[j];
        float w = g_cattr[j];
        float2 xlv = ((const float2*)(xl + srcn * 64))[lane];
        float e0 = xlv.x + xrv.x + w * Wev.x;
        float e1 = xlv.y + xrv.y + w * Wev.y;
        float l0 = (e0 > 0.f) ? e0 : 0.2f * e0;
        float l1 = (e1 > 0.f) ? e1 : 0.2f * e1;
        float t = l0 * attv.x + l1 * attv.y;
        #pragma unroll
        for (int o = 16; o; o >>= 1) t += __shfl_xor_sync(0xffffffffu, t, o);
        float nm = fmaxf(m, t);
        float scale = __expf(m - nm);
        float p = __expf(t - nm);
        s = s * scale + p;
        a0 = a0 * scale + p * xlv.x;
        a1 = a1 * scale + p * xlv.y;
        m = nm;
    }
    float inv = 1.f / s;
    float2 bov = __ldg(((const float2*)bo) + lane);
    float2 o;
    o.x = a0 * inv + bov.x;
    o.y = a1 * inv + bov.y;
    ((float2*)(out + node * 64))[lane] = o;
}

// ---------------- final layer (C -> 1) + mean pool --------------------------
__global__ void gemm8_kernel(const float* __restrict__ x,
                             const float* __restrict__ Wl, const float* __restrict__ bl,
                             const float* __restrict__ Wr, const float* __restrict__ br,
                             int n)
{
    int w = (blockIdx.x * blockDim.x + threadIdx.x) >> 5;
    int lane = threadIdx.x & 31;
    if (w >= n) return;
    float2 xv = ((const float2*)(x + w * 64))[lane];
    float2 wl = __ldg(((const float2*)Wl) + lane);
    float2 wr = __ldg(((const float2*)Wr) + lane);
    float tl = xv.x * wl.x + xv.y * wl.y;
    float tr = xv.x * wr.x + xv.y * wr.y;
    #pragma unroll
    for (int o = 16; o; o >>= 1) {
        tl += __shfl_xor_sync(0xffffffffu, tl, o);
        tr += __shfl_xor_sync(0xffffffffu, tr, o);
    }
    if (lane == 0) {
        g_xl8[w] = tl + __ldg(bl);
        g_xr8[w] = tr + __ldg(br);
    }
}

__global__ __launch_bounds__(256) void aggr8_kernel(
    const float* __restrict__ We8, const float* __restrict__ att8,
    const float* __restrict__ bo8, float* __restrict__ out, int n)
{
    int i = blockIdx.x * blockDim.x + threadIdx.x;
    float r = 0.f;
    if (i < n) {
        float wev = __ldg(We8);
        float attv = __ldg(att8);
        float xrv = g_xr8[i];
        int beg = g_offs[i], end = g_offs[i + 1];
        float m = -3.0e38f, s = 0.f, acc = 0.f;
        for (int j = beg; j < end; ++j) {
            int sn = g_csrc[j];
            float w = g_cattr[j];
            float xls = g_xl8[sn];
            float e = xls + xrv + w * wev;
            float l = (e > 0.f) ? e : 0.2f * e;
            float t = l * attv;
            float nm = fmaxf(m, t);
            float scale = __expf(m - nm);
            float p = __expf(t - nm);
            s = s * scale + p;
            acc = acc * scale + p * xls;
            m = nm;
        }
        r = (acc / s + __ldg(bo8)) / (float)n;
    }
    __shared__ float red[256];
    red[threadIdx.x] = r;
    __syncthreads();
    for (int st = 128; st; st >>= 1) {
        if (threadIdx.x < st) red[threadIdx.x] += red[threadIdx.x + st];
        __syncthreads();
    }
    if (threadIdx.x == 0) atomicAdd(out, red[0]);
}

// ---------------- host launch ------------------------------------------------
static float* sym_f(const void* s) { void* p = nullptr; cudaGetSymbolAddress(&p, s); return (float*)p; }

extern "C" void kernel_launch(void* const* d_in, const int* in_sizes, int n_in,
                              void* d_out, int out_size)
{
    const float* features = (const float*)d_in[0];
    const int*   e_src    = (const int*)d_in[1];
    const int*   e_dst    = (const int*)d_in[2];
    const float* e_w      = (const float*)d_in[3];
    const float* Wl1 = (const float*)d_in[4];  const float* bl1 = (const float*)d_in[5];
    const float* Wr1 = (const float*)d_in[6];  const float* br1 = (const float*)d_in[7];
    const float* We1 = (const float*)d_in[8];  const float* att1 = (const float*)d_in[9];
    const float* bo1 = (const float*)d_in[10];
    const float* Wlm = (const float*)d_in[11]; const float* blm = (const float*)d_in[12];
    const float* Wrm = (const float*)d_in[13]; const float* brm = (const float*)d_in[14];
    const float* Wem = (const float*)d_in[15]; const float* attm = (const float*)d_in[16];
    const float* bom = (const float*)d_in[17];
    const float* Wl8 = (const float*)d_in[18]; const float* bl8 = (const float*)d_in[19];
    const float* Wr8 = (const float*)d_in[20]; const float* br8 = (const float*)d_in[21];
    const float* We8 = (const float*)d_in[22]; const float* att8 = (const float*)d_in[23];
    const float* bo8 = (const float*)d_in[24];

    int n = in_sizes[0] / C;
    int e = in_sizes[1];
    float* out = (float*)d_out;

    float* x0 = sym_f(g_x0);
    float* x1 = sym_f(g_x1);
    float* xl = sym_f(g_xl);
    float* xr = sym_f(g_xr);

    int nb = (n + 255) / 256;
    int eb = (e + 255) / 256;

    // build CSR(dst) + self-loop mean attrs
    zero_kernel<<<nb, 256>>>(out, n);
    hist_kernel<<<eb, 256>>>(e_dst, e_w, e);
    loop_attr_kernel<<<nb, 256>>>(n);
    scan_kernel<<<1, 1024>>>(n);
    cursor_kernel<<<nb, 256>>>(n);
    scatter_edges_kernel<<<eb, 256>>>(e_src, e_dst, e_w, e);
    scatter_loops_kernel<<<nb, 256>>>(n);

    int gemm_blocks = (n + 31) / 32;
    int aggr_blocks = (n * 32 + 255) / 256;

    // layer 1
    gemm_xlxr_kernel<<<gemm_blocks, 256>>>(features, Wl1, bl1, Wr1, br1, xl, xr, n);
    aggr_kernel<<<aggr_blocks, 256>>>(xl, xr, We1, att1, bo1, x0, n);

    // layers 2..7
    float* cur = x0;
    float* nxt = x1;
    for (int i = 0; i < 6; i++) {
        gemm_xlxr_kernel<<<gemm_blocks, 256>>>(cur, Wlm + i * 4096, blm + i * 64,
                                               Wrm + i * 4096, brm + i * 64, xl, xr, n);
        aggr_kernel<<<aggr_blocks, 256>>>(xl, xr, Wem + i * 64, attm + i * 64,
                                          bom + i * 64, nxt, n);
        float* t = cur; cur = nxt; nxt = t;
    }

    // layer 8 (C -> 1) + mean pool
    gemm8_kernel<<<(n * 32 + 255) / 256, 256>>>(cur, Wl8, bl8, Wr8, br8, n);
    aggr8_kernel<<<nb, 256>>>(We8, att8, bo8, out, n);
}